// round 4
// baseline (speedup 1.0000x reference)
#include <cuda_runtime.h>
#include <cstdint>
#include <math.h>

#define NT 1024
#define NH 1024
#define NF 4096
#define NE 8
#define NK 2

// ---- device scratch ----
__device__ int   g_sel [NT*NK];
__device__ float g_rw  [NT*NK];
__device__ int   g_slot[NT*NK];
__device__ int   g_cnt [NE];
__device__ int   g_off [NE];
__device__ int   g_tok [NT*NK];
__device__ float g_h[(size_t)(NT*NK)*NF];
__device__ float g_y[2][(size_t)(NT*NK)*NH];

// ---- helpers ----
__device__ __forceinline__ uint32_t smem_u32(const void* p){
    uint32_t a; asm("{ .reg .u64 t; cvta.to.shared.u64 t, %1; cvt.u32.u64 %0, t; }":"=r"(a):"l"(p)); return a;
}
__device__ __forceinline__ void cpa16(uint32_t s, const void* g){
    asm volatile("cp.async.cg.shared.global [%0], [%1], 16;"::"r"(s),"l"(g));
}
__device__ __forceinline__ void cpa_commit(){ asm volatile("cp.async.commit_group;"); }
template<int N> __device__ __forceinline__ void cpa_wait(){ asm volatile("cp.async.wait_group %0;"::"n"(N)); }
__device__ __forceinline__ uint32_t f2tf(float f){
    uint32_t r; asm("cvt.rna.tf32.f32 %0, %1;":"=r"(r):"f"(f)); return r;
}
__device__ __forceinline__ void mma8(float* d, const uint32_t* a, const uint32_t* b){
    asm volatile("mma.sync.aligned.m16n8k8.row.col.f32.tf32.tf32.f32 "
        "{%0,%1,%2,%3}, {%4,%5,%6,%7}, {%8,%9}, {%0,%1,%2,%3};"
        : "+f"(d[0]),"+f"(d[1]),"+f"(d[2]),"+f"(d[3])
        : "r"(a[0]),"r"(a[1]),"r"(a[2]),"r"(a[3]),"r"(b[0]),"r"(b[1]));
}
__device__ __forceinline__ float gelu_exact(float v){
    return 0.5f * v * (1.0f + erff(v * 0.70710678118654752f));
}

// ---- aux kernels ----
__global__ void init_kernel(){
    int i = threadIdx.x;
    if (i < NE) g_cnt[i] = 0;
}

__global__ void router_kernel(const float* __restrict__ x,
                              const float* __restrict__ gw,
                              const float* __restrict__ gb){
    __shared__ float4 sg[NE*NH/4];
    int tid = threadIdx.x;
    for (int i = tid; i < NE*NH/4; i += blockDim.x) sg[i] = ((const float4*)gw)[i];
    __syncthreads();
    int t = blockIdx.x*blockDim.x + tid;
    const float4* xr = (const float4*)(x + (size_t)t*NH);
    float acc[NE];
#pragma unroll
    for (int e=0;e<NE;e++) acc[e] = gb[e];
    for (int i=0;i<NH/4;i++){
        float4 xv = xr[i];
#pragma unroll
        for (int e=0;e<NE;e++){
            float4 g = sg[e*(NH/4)+i];
            acc[e] += xv.x*g.x + xv.y*g.y + xv.z*g.z + xv.w*g.w;
        }
    }
    int i0=0; float l0=acc[0];
#pragma unroll
    for (int e=1;e<NE;e++) if (acc[e]>l0){ l0=acc[e]; i0=e; }
    int i1=-1; float l1=-3.4e38f;
#pragma unroll
    for (int e=0;e<NE;e++) if (e!=i0 && acc[e]>l1){ l1=acc[e]; i1=e; }
    float p0 = 1.0f/(1.0f+expf(l1-l0));
    g_sel[t*2+0]=i0; g_sel[t*2+1]=i1;
    g_rw [t*2+0]=p0; g_rw [t*2+1]=1.0f-p0;
    atomicAdd(&g_cnt[i0],1);
    atomicAdd(&g_cnt[i1],1);
}

// single block: exclusive scan of 8 counts, then scatter all 2048 assignments
__global__ void scanfill_kernel(){
    __shared__ int scur[NE];
    int tid = threadIdx.x;
    if (tid == 0){
        int o = 0;
        for (int e=0;e<NE;e++){ g_off[e]=o; scur[e]=0; o += g_cnt[e]; }
    }
    __syncthreads();
    for (int t = tid; t < NT; t += blockDim.x){
        for (int k=0;k<NK;k++){
            int e = g_sel[t*2+k];
            int pos = atomicAdd(&scur[e],1);
            int idx = g_off[e]+pos;
            g_tok[idx]    = t;
            g_slot[t*2+k] = idx;
        }
    }
}

// ---- grouped tf32 mma.sync GEMM ----
// CTA tile 128x256, BK=32, 256 threads = 8 warps (2m x 4n) of 64x64.
// 4-stage cp.async pipeline, fragment double-buffering across ksteps.
// MODE 1: g_h[slot] = gelu(x[tok] @ w1[e] + b1[e])   K=1024, ldB=NF
// MODE 2: g_y[ks][slot] = g_h[slot] @ w2[e] (splitK2) K=2048, ldB=NH

#define ASTR 36
#define BSTR 264
#define STG_A (128*ASTR)
#define STG_B (32*BSTR)
#define STG_F (STG_A + STG_B)       // 13056 floats
#define NSTG  4
#define SMEM_SZ (NSTG*STG_F*4)      // 208896 bytes

template<int MODE>
__global__ __launch_bounds__(256, 1)
void moe_gemm(const float* __restrict__ Asrc,
              const float* __restrict__ W,
              const float* __restrict__ bias){
    const int z   = blockIdx.z;
    const int e   = (MODE==1) ? z : (z & 7);
    const int ks  = (MODE==1) ? 0 : (z >> 3);
    const int cnt = g_cnt[e];
    const int m0  = blockIdx.y * 128;
    if (m0 >= cnt) return;
    const int off = g_off[e];
    const int n0  = blockIdx.x * 256;
    const int ldB = (MODE==1) ? NF : NH;
    const int Kfull = (MODE==1) ? NH : NF;
    const int Kloc  = (MODE==1) ? NH : NF/2;
    const int k0    = (MODE==1) ? 0  : ks * (NF/2);
    const int KT    = Kloc / 32;

    extern __shared__ float smem[];
    const uint32_t sb = smem_u32(smem);
    const int tid = threadIdx.x, wid = tid>>5, lane = tid&31;
    const int g = lane>>2, tg = lane&3;
    const int wm = wid&1, wn = wid>>1;

    // ---- A load mapping: thread -> row tid>>1, cols (tid&1)*16 + j*4 (j=0..3)
    {
        // nothing
    }
    const int arow_l = tid>>1;
    const int acol   = (tid&1)*16;
    int mi = m0 + arow_l;
    int ci = (mi < cnt) ? mi : (cnt-1);
    const float* aptr;
    if (MODE==1) aptr = Asrc + (size_t)g_tok[off+ci]*NH + acol;
    else         aptr = Asrc + (size_t)(off+ci)*NF + k0 + acol;

    // ---- B load mapping: thread -> row tid>>3, cols (tid&7)*4 + j*32 (j=0..7)
    const int brow = tid>>3;
    const int bcol = (tid&7)*4;
    const float* bptr = W + (size_t)e*Kfull*ldB + (size_t)(k0 + brow)*ldB + n0 + bcol;

    const uint32_t adst = sb + ((uint32_t)(arow_l*ASTR + acol))*4u;
    const uint32_t bdst = sb + ((uint32_t)(STG_A + brow*BSTR + bcol))*4u;

    auto load_stage = [&](int s, int kt){
        uint32_t ab = adst + (uint32_t)s*STG_F*4u;
        uint32_t bb = bdst + (uint32_t)s*STG_F*4u;
        const float* ga = aptr + kt*32;
        const float* gbp = bptr + (size_t)kt*32*ldB;
#pragma unroll
        for (int j=0;j<4;j++) cpa16(ab + j*16u, ga + j*4);
#pragma unroll
        for (int j=0;j<8;j++) cpa16(bb + j*128u, gbp + j*32);
    };

    load_stage(0,0); cpa_commit();
    load_stage(1,1); cpa_commit();
    load_stage(2,2); cpa_commit();

    float acc[4][8][4];
#pragma unroll
    for (int i=0;i<4;i++)
#pragma unroll
        for (int j=0;j<8;j++)
#pragma unroll
            for (int r=0;r<4;r++) acc[i][j][r] = 0.0f;

    uint32_t af[2][4][4], bf[2][8][2];

    auto load_frags = [&](const float* sA, const float* sB, int kstep, int buf){
#pragma unroll
        for (int i=0;i<4;i++){
            const float* pa = sA + (wm*64 + i*16 + g)*ASTR + kstep*8 + tg;
            af[buf][i][0] = f2tf(pa[0]);
            af[buf][i][1] = f2tf(pa[8*ASTR]);
            af[buf][i][2] = f2tf(pa[4]);
            af[buf][i][3] = f2tf(pa[8*ASTR+4]);
        }
#pragma unroll
        for (int j=0;j<8;j++){
            const float* pb = sB + (kstep*8 + tg)*BSTR + wn*64 + j*8 + g;
            bf[buf][j][0] = f2tf(pb[0]);
            bf[buf][j][1] = f2tf(pb[4*BSTR]);
        }
    };

    for (int kt = 0; kt < KT; kt++){
        cpa_wait<2>();
        __syncthreads();
        // prefetch next stage early (stage (kt+3)%4 == (kt-1)%4: safe, all warps
        // finished computing kt-1 before the sync above)
        if (kt + 3 < KT) load_stage((kt+3)%NSTG, kt+3);
        cpa_commit();

        const float* sA = smem + (kt%NSTG)*STG_F;
        const float* sB = sA + STG_A;
        load_frags(sA, sB, 0, 0);
#pragma unroll
        for (int kstep=0;kstep<4;kstep++){
            int cur = kstep&1, nxt = cur^1;
            if (kstep < 3) load_frags(sA, sB, kstep+1, nxt);
#pragma unroll
            for (int i=0;i<4;i++)
#pragma unroll
                for (int j=0;j<8;j++)
                    mma8(acc[i][j], af[cur][i], bf[cur][j]);
        }
    }

    // ---- epilogue ----
    if (MODE == 1){
        const float* bp = bias + (size_t)e*NF + n0 + wn*64;
#pragma unroll
        for (int i=0;i<4;i++){
            int r0 = m0 + wm*64 + i*16 + g;
            int r1 = r0 + 8;
#pragma unroll
            for (int j=0;j<8;j++){
                int c = j*8 + tg*2;
                float b0 = __ldg(bp + c), b1v = __ldg(bp + c + 1);
                if (r0 < cnt){
                    float* o = g_h + (size_t)(off+r0)*NF + n0 + wn*64 + c;
                    float2 v; v.x = gelu_exact(acc[i][j][0] + b0);
                              v.y = gelu_exact(acc[i][j][1] + b1v);
                    *(float2*)o = v;
                }
                if (r1 < cnt){
                    float* o = g_h + (size_t)(off+r1)*NF + n0 + wn*64 + c;
                    float2 v; v.x = gelu_exact(acc[i][j][2] + b0);
                              v.y = gelu_exact(acc[i][j][3] + b1v);
                    *(float2*)o = v;
                }
            }
        }
    } else {
        float* Yb = g_y[ks];
#pragma unroll
        for (int i=0;i<4;i++){
            int r0 = m0 + wm*64 + i*16 + g;
            int r1 = r0 + 8;
#pragma unroll
            for (int j=0;j<8;j++){
                int c = n0 + wn*64 + j*8 + tg*2;
                if (r0 < cnt)
                    *(float2*)(Yb + (size_t)(off+r0)*NH + c) = make_float2(acc[i][j][0], acc[i][j][1]);
                if (r1 < cnt)
                    *(float2*)(Yb + (size_t)(off+r1)*NH + c) = make_float2(acc[i][j][2], acc[i][j][3]);
            }
        }
    }
}

// ---- combine ----
__global__ void combine_kernel(const float* __restrict__ b2, float* __restrict__ out){
    int idx = blockIdx.x*blockDim.x + threadIdx.x;
    int t  = idx >> 8;
    int h4 = (idx & 255) * 4;
    float4 a = make_float4(0.f,0.f,0.f,0.f);
#pragma unroll
    for (int k=0;k<2;k++){
        int e = g_sel[t*2+k];
        float w = g_rw[t*2+k];
        int sl = g_slot[t*2+k];
        float4 y0 = *(const float4*)&g_y[0][(size_t)sl*NH + h4];
        float4 y1 = *(const float4*)&g_y[1][(size_t)sl*NH + h4];
        float4 bb = *(const float4*)&b2[(size_t)e*NH + h4];
        a.x += w*(y0.x+y1.x+bb.x);
        a.y += w*(y0.y+y1.y+bb.y);
        a.z += w*(y0.z+y1.z+bb.z);
        a.w += w*(y0.w+y1.w+bb.w);
    }
    *(float4*)&out[(size_t)t*NH + h4] = a;
}

extern "C" void kernel_launch(void* const* d_in, const int* in_sizes, int n_in,
                              void* d_out, int out_size){
    const float* x  = (const float*)d_in[0];
    const float* gw = (const float*)d_in[1];
    const float* gb = (const float*)d_in[2];
    const float* w1 = (const float*)d_in[3];
    const float* b1 = (const float*)d_in[4];
    const float* w2 = (const float*)d_in[5];
    const float* b2 = (const float*)d_in[6];
    float* out = (float*)d_out;

    cudaFuncSetAttribute(moe_gemm<1>, cudaFuncAttributeMaxDynamicSharedMemorySize, SMEM_SZ);
    cudaFuncSetAttribute(moe_gemm<2>, cudaFuncAttributeMaxDynamicSharedMemorySize, SMEM_SZ);

    void* ghp = nullptr;
    cudaGetSymbolAddress(&ghp, g_h);

    init_kernel<<<1, 32>>>();                       // our launch 0
    router_kernel<<<NT/128, 128>>>(x, gw, gb);      // 1
    scanfill_kernel<<<1, 1024>>>();                 // 2
    dim3 g1(NF/256, 8, NE);
    moe_gemm<1><<<g1, 256, SMEM_SZ>>>(x, w1, b1);   // 3  <- ncu capture slot
    dim3 g2(NH/256, 8, NE*2);
    moe_gemm<2><<<g2, 256, SMEM_SZ>>>((const float*)ghp, w2, nullptr);  // 4
    combine_kernel<<<(NT*NH/4)/256, 256>>>(b2, out);                    // 5
}